// round 1
// baseline (speedup 1.0000x reference)
#include <cuda_runtime.h>
#include <math.h>

// Problem constants
#define NB   2
#define L    2048
#define H    8
#define D    64
#define HD   512            // H*D
#define LHD  1048576        // L*H*D
#define P    16             // NB*H pairs
#define C    64             // chunk length
#define NC   32             // L/C
#define EPSF 1e-6f

// ---------------- scratch (device globals; no allocation) ----------------
__device__ float g_sq[P*L*D];      // sigmoid(q), later overwritten with q_scaled
__device__ float g_sk[P*L*D];      // sigmoid(k)
__device__ float g_vs[P*L*D];      // v * source_competition
__device__ float g_ksum[P*NC*D];   // chunk sums of sk -> exclusive prefix (in place)
__device__ float g_qsum[P*NC*D];
__device__ float g_kso[P*NC*D];    // chunk sums of sk*so -> exclusive prefix
__device__ float g_qsi[P*NC*D];
__device__ float g_si[P*L];
__device__ float g_so[P*L];
__device__ float g_sa[P*L];        // sink_allocation
__device__ float g_es[P*L];        // exp(conserved_source)
__device__ float g_essum[P*NC];    // chunk sums of es -> exclusive prefix
__device__ float g_kvc[P*NC*D*D];  // chunk KV sums -> exclusive prefix

__device__ __forceinline__ float sigmoidf_(float x){ return 1.f/(1.f+__expf(-x)); }

// ---------------- K1: sigmoid + chunk sums ----------------
__global__ void k_prep(const float* __restrict__ Q, const float* __restrict__ K){
  int c = blockIdx.x, p = blockIdx.y, d = threadIdx.x;
  const float* Qp = Q + (size_t)(p>>3)*LHD + (size_t)(p&7)*D + d;
  const float* Kp = K + (size_t)(p>>3)*LHD + (size_t)(p&7)*D + d;
  int l0 = c*C;
  int ob = (p*L + l0)*D + d;
  float ks = 0.f, qs = 0.f;
  for(int j=0;j<C;j++){
    float qv = sigmoidf_(Qp[(size_t)(l0+j)*HD]);
    float kv = sigmoidf_(Kp[(size_t)(l0+j)*HD]);
    g_sq[ob + j*D] = qv;
    g_sk[ob + j*D] = kv;
    qs += qv; ks += kv;
  }
  g_ksum[(p*NC+c)*D+d] = ks;
  g_qsum[(p*NC+c)*D+d] = qs;
}

// ---------------- K2/K4: exclusive scan of per-d chunk sums ----------------
__global__ void k_scan_kq(){
  int p = blockIdx.x, t = threadIdx.x;
  float* arr = (t < D) ? g_ksum : g_qsum;
  int d = t & (D-1);
  float run = 0.f;
  for(int c=0;c<NC;c++){
    int idx = (p*NC+c)*D + d;
    float v = arr[idx]; arr[idx] = run; run += v;
  }
}
__global__ void k_scan_cons(){
  int p = blockIdx.x, t = threadIdx.x;
  float* arr = (t < D) ? g_kso : g_qsi;
  int d = t & (D-1);
  float run = 0.f;
  for(int c=0;c<NC;c++){
    int idx = (p*NC+c)*D + d;
    float v = arr[idx]; arr[idx] = run; run += v;
  }
}

// ---------------- K3: sink_incoming / source_outgoing ----------------
// smem: sq tile (4096) | sk tile (4096) | S^T (64*65)
__global__ void k_siso(){
  extern __shared__ float sm[];
  float* sq_s = sm;
  float* sk_s = sm + 4096;
  float* Ssm  = sm + 8192;            // Ssm[a*65+b] = S[b][a]
  __shared__ float rsk[C], rsq[C], sis[C], sos[C], kpre[D], qpre[D];
  int c = blockIdx.x, p = blockIdx.y, l = threadIdx.x;
  int base_ld = (p*L + c*C)*D;
  for(int e=l; e<C*D; e+=C){ sq_s[e]=g_sq[base_ld+e]; sk_s[e]=g_sk[base_ld+e]; }
  kpre[l] = g_ksum[(p*NC+c)*D + l];
  qpre[l] = g_qsum[(p*NC+c)*D + l];
  __syncthreads();

  float rk=0.f, rq=0.f, b1=0.f, b2=0.f;
  for(int d=0;d<D;d++){
    float sq = sq_s[l*D+d], sk = sk_s[l*D+d];
    rk += sk; rq += sq;
    b1 += (sq+EPSF)*(kpre[d]+EPSF);
    b2 += (sk+EPSF)*(qpre[d]+EPSF);
  }
  rsk[l]=rk; rsq[l]=rq;

  float acc[C];
  #pragma unroll
  for(int j=0;j<C;j++) acc[j]=0.f;
  for(int dd=0; dd<D; dd+=4){
    float4 q4 = *(const float4*)(sq_s + l*D + dd);
    #pragma unroll
    for(int j=0;j<C;j++){
      float4 k4 = *(const float4*)(sk_s + j*D + dd);
      acc[j] = fmaf(q4.x,k4.x, fmaf(q4.y,k4.y, fmaf(q4.z,k4.z, fmaf(q4.w,k4.w, acc[j]))));
    }
  }
  #pragma unroll
  for(int j=0;j<C;j++) Ssm[j*65 + l] = acc[j];   // store S transposed
  __syncthreads();

  float dot1 = b1, dot2 = b2;
  #pragma unroll
  for(int i=0;i<C;i++){
    if(i<=l){
      dot1 += acc[i]        + EPSF*rsk[i];
      dot2 += Ssm[l*65 + i] + EPSF*rsq[i];      // = S[i][l]
    }
  }
  float nrm = (float)(c*C + l + 1);
  float si = nrm/dot1, so = nrm/dot2;
  sis[l]=si; sos[l]=so;
  g_si[p*L + c*C + l] = si;
  g_so[p*L + c*C + l] = so;
  __syncthreads();

  // chunk sums of sk*so and sq*si (thread = d)
  int d = l;
  float a1=0.f, a2=0.f;
  for(int j=0;j<C;j++){ a1 += sk_s[j*D+d]*sos[j]; a2 += sq_s[j*D+d]*sis[j]; }
  g_kso[(p*NC+c)*D+d] = a1;
  g_qsi[(p*NC+c)*D+d] = a2;
}

// ---------------- K5: conserved sink/source, sa, es, q_scaled ----------------
__global__ void k_conserved(){
  extern __shared__ float sm[];
  float* sq_s = sm;
  float* sk_s = sm + 4096;
  float* Ssm  = sm + 8192;
  __shared__ float rsk[C], rsq[C], sis[C], sos[C], kpre[D], qpre[D], fac[C], essh[C];
  int c = blockIdx.x, p = blockIdx.y, l = threadIdx.x;
  int base_ld = (p*L + c*C)*D;
  for(int e=l; e<C*D; e+=C){ sq_s[e]=g_sq[base_ld+e]; sk_s[e]=g_sk[base_ld+e]; }
  kpre[l] = g_kso[(p*NC+c)*D + l];
  qpre[l] = g_qsi[(p*NC+c)*D + l];
  sis[l]  = g_si[p*L + c*C + l];
  sos[l]  = g_so[p*L + c*C + l];
  __syncthreads();

  float rk=0.f, rq=0.f, b3=0.f, b4=0.f;
  for(int d=0;d<D;d++){
    float sq = sq_s[l*D+d], sk = sk_s[l*D+d];
    rk += sk; rq += sq;
    b3 += (sq+EPSF)*(kpre[d]+EPSF);
    b4 += (sk+EPSF)*(qpre[d]+EPSF);
  }
  rsk[l]=rk; rsq[l]=rq;

  float acc[C];
  #pragma unroll
  for(int j=0;j<C;j++) acc[j]=0.f;
  for(int dd=0; dd<D; dd+=4){
    float4 q4 = *(const float4*)(sq_s + l*D + dd);
    #pragma unroll
    for(int j=0;j<C;j++){
      float4 k4 = *(const float4*)(sk_s + j*D + dd);
      acc[j] = fmaf(q4.x,k4.x, fmaf(q4.y,k4.y, fmaf(q4.z,k4.z, fmaf(q4.w,k4.w, acc[j]))));
    }
  }
  #pragma unroll
  for(int j=0;j<C;j++) Ssm[j*65 + l] = acc[j];
  __syncthreads();

  float dot3 = b3, dot4 = b4;
  #pragma unroll
  for(int i=0;i<C;i++){
    if(i<=l){
      dot3 += sos[i]*(acc[i]        + EPSF*rsk[i]);
      dot4 += sis[i]*(Ssm[l*65 + i] + EPSF*rsq[i]);
    }
  }
  float nrm = (float)(c*C + l + 1);
  float cs  = dot3/nrm;
  float sa  = sigmoidf_(cs);
  float cso = dot4/nrm;
  cso = fminf(1.f, fmaxf(-1.f, cso));
  float es  = __expf(cso);
  g_sa[p*L + c*C + l] = sa;
  g_es[p*L + c*C + l] = es;
  fac[l]  = sis[l]/nrm;     // si/normal -> q_scaled factor
  essh[l] = es;
  __syncthreads();

  // overwrite g_sq with q_scaled (coalesced)
  for(int e=l; e<C*D; e+=C) g_sq[base_ld+e] = sq_s[e]*fac[e>>6];
  if(l==0){
    float s=0.f;
    for(int j=0;j<C;j++) s += essh[j];
    g_essum[p*NC+c] = s;
  }
}

// ---------------- K6: scan es chunk sums ----------------
__global__ void k_scan_es(){
  int p = threadIdx.x;
  if(p < P){
    float run = 0.f;
    for(int c=0;c<NC;c++){
      float v = g_essum[p*NC+c]; g_essum[p*NC+c] = run; run += v;
    }
  }
}

// ---------------- K7: v_scaled + chunk KV sums ----------------
__global__ void k_vkv(const float* __restrict__ V){
  __shared__ float sk_s[C*D], vs_s[C*D], ess[C], comp[C];
  int c = blockIdx.x, p = blockIdx.y, t = threadIdx.x;
  int base_ld = (p*L + c*C)*D;
  for(int e=t; e<C*D; e+=C) sk_s[e] = g_sk[base_ld+e];
  ess[t] = g_es[p*L + c*C + t];
  __syncthreads();
  if(t==0){
    float run = g_essum[p*NC+c];
    for(int j=0;j<C;j++){
      run += ess[j];
      comp[j] = ess[j]/run*(float)(c*C + j + 1);
    }
  }
  __syncthreads();
  const float* Vp = V + (size_t)(p>>3)*LHD + (size_t)(p&7)*D;
  for(int e=t; e<C*D; e+=C){
    int j = e>>6, d2 = e&63;
    float x = Vp[(size_t)(c*C+j)*HD + d2]*comp[j];
    vs_s[e] = x;
    g_vs[base_ld+e] = x;
  }
  __syncthreads();
  // KV chunk sum: thread t = d row
  float accm[D];
  #pragma unroll
  for(int m=0;m<D;m++) accm[m]=0.f;
  for(int j=0;j<C;j++){
    float a = sk_s[j*D+t];
    #pragma unroll
    for(int m=0;m<D;m++) accm[m] = fmaf(a, vs_s[j*D+m], accm[m]);
  }
  float* dst = g_kvc + ((size_t)(p*NC+c)*D + t)*D;
  #pragma unroll
  for(int m=0;m<D;m+=4)
    *(float4*)(dst+m) = make_float4(accm[m],accm[m+1],accm[m+2],accm[m+3]);
}

// ---------------- K8: scan chunk KV sums ----------------
__global__ void k_scan_kv(){
  int p = blockIdx.x;
  for(int e=threadIdx.x; e<D*D; e+=256){
    float run = 0.f;
    for(int c=0;c<NC;c++){
      size_t idx = (size_t)(p*NC+c)*D*D + e;
      float v = g_kvc[idx]; g_kvc[idx] = run; run += v;
    }
  }
}

// ---------------- K9: causal output ----------------
// smem: qs | sk | vs | kvprefix  (4 x 4096 floats)
__global__ void k_out(float* __restrict__ OUT){
  extern __shared__ float sm[];
  float* qs_s = sm;
  float* sk_s = sm + 4096;
  float* vs_s = sm + 8192;
  float* kv_s = sm + 12288;
  __shared__ float sa_s[C];
  int c = blockIdx.x, p = blockIdx.y, l = threadIdx.x;
  int base_ld = (p*L + c*C)*D;
  for(int e=l; e<C*D; e+=C){
    qs_s[e] = g_sq[base_ld+e];
    sk_s[e] = g_sk[base_ld+e];
    vs_s[e] = g_vs[base_ld+e];
    kv_s[e] = g_kvc[(size_t)(p*NC+c)*D*D + e];
  }
  sa_s[l] = g_sa[p*L + c*C + l];
  __syncthreads();

  // T row: acc[i] = qs[l] . sk[i]
  float acc[C];
  #pragma unroll
  for(int j=0;j<C;j++) acc[j]=0.f;
  for(int dd=0; dd<D; dd+=4){
    float4 q4 = *(const float4*)(qs_s + l*D + dd);
    #pragma unroll
    for(int j=0;j<C;j++){
      float4 k4 = *(const float4*)(sk_s + j*D + dd);
      acc[j] = fmaf(q4.x,k4.x, fmaf(q4.y,k4.y, fmaf(q4.z,k4.z, fmaf(q4.w,k4.w, acc[j]))));
    }
  }

  float o[D];
  #pragma unroll
  for(int m=0;m<D;m++) o[m]=0.f;
  // intra-chunk causal part
  #pragma unroll
  for(int i=0;i<C;i++){
    if(i<=l){
      float t = acc[i];
      #pragma unroll
      for(int m=0;m<D;m++) o[m] = fmaf(t, vs_s[i*D+m], o[m]);
    }
  }
  // inter-chunk part: qs[l] @ KVprefix
  for(int d=0;d<D;d++){
    float qd = qs_s[l*D+d];
    #pragma unroll
    for(int m=0;m<D;m++) o[m] = fmaf(qd, kv_s[d*D+m], o[m]);
  }
  float sa = sa_s[l];
  float* op = OUT + (size_t)(p>>3)*LHD + (size_t)(c*C+l)*HD + (size_t)(p&7)*D;
  #pragma unroll
  for(int m=0;m<D;m+=4){
    float4 r = make_float4(o[m]*sa, o[m+1]*sa, o[m+2]*sa, o[m+3]*sa);
    *(float4*)(op+m) = r;
  }
}

// ---------------- launch ----------------
extern "C" void kernel_launch(void* const* d_in, const int* in_sizes, int n_in,
                              void* d_out, int out_size){
  const float* Q = (const float*)d_in[0];
  const float* K = (const float*)d_in[1];
  const float* V = (const float*)d_in[2];
  float* OUT = (float*)d_out;

  const int SMEM_SISO = (4096+4096+64*65)*sizeof(float);   // 49408 B
  const int SMEM_OUT  = (4*4096)*sizeof(float);            // 65536 B
  cudaFuncSetAttribute(k_siso,      cudaFuncAttributeMaxDynamicSharedMemorySize, SMEM_SISO);
  cudaFuncSetAttribute(k_conserved, cudaFuncAttributeMaxDynamicSharedMemorySize, SMEM_SISO);
  cudaFuncSetAttribute(k_out,       cudaFuncAttributeMaxDynamicSharedMemorySize, SMEM_OUT);

  dim3 gpc(NC, P);
  k_prep<<<gpc, D>>>(Q, K);
  k_scan_kq<<<P, 2*D>>>();
  k_siso<<<gpc, C, SMEM_SISO>>>();
  k_scan_cons<<<P, 2*D>>>();
  k_conserved<<<gpc, C, SMEM_SISO>>>();
  k_scan_es<<<1, P>>>();
  k_vkv<<<gpc, C>>>(V);
  k_scan_kv<<<P, 256>>>();
  k_out<<<gpc, C, SMEM_OUT>>>(OUT);
}

// round 2
// speedup vs baseline: 1.4930x; 1.4930x over previous
#include <cuda_runtime.h>
#include <math.h>
#include <stdint.h>

// Problem constants
#define NB   2
#define L    2048
#define H    8
#define D    64
#define HD   512
#define LHD  1048576
#define P    16
#define C    64
#define NC   32
#define EPSF 1e-6f
#define SD   68      // padded smem row stride (floats)

// ---------------- scratch (device globals; no allocation) ----------------
__device__ float g_sq[P*L*D];      // sigmoid(q); overwritten with q_scaled by k_conserved
__device__ float g_sk[P*L*D];      // sigmoid(k)
__device__ float g_vs[P*L*D];      // v * source_competition
__device__ float g_ST[P*NC*C*C];   // per-chunk gram, transposed: ST[j*64+l] = S[l][j] = q_l . k_j
__device__ float g_ksum[P*NC*D];   // per-chunk sums of sk
__device__ float g_qsum[P*NC*D];
__device__ float g_kso[P*NC*D];    // per-chunk sums of sk*so
__device__ float g_qsi[P*NC*D];
__device__ float g_si[P*L];
__device__ float g_so[P*L];
__device__ float g_rk[P*L];        // row sums of sk
__device__ float g_rq[P*L];
__device__ float g_sa[P*L];
__device__ float g_es[P*L];
__device__ float g_essum[P*NC];
__device__ float g_kvc[P*NC*D*D];  // chunk KV sums -> exclusive prefix (in place)

// ---------------- f32x2 packed-FMA helpers (sm_103a) ----------------
__device__ __forceinline__ unsigned long long pack2(float a, float b){
  unsigned long long r;
  asm("mov.b64 %0, {%1,%2};" : "=l"(r) : "f"(a), "f"(b));
  return r;
}
__device__ __forceinline__ void fma2(unsigned long long &acc, unsigned long long a, unsigned long long b){
  asm("fma.rn.f32x2 %0, %1, %2, %0;" : "+l"(acc) : "l"(a), "l"(b));
}
__device__ __forceinline__ float2 unpack2(unsigned long long v){
  float2 r;
  asm("mov.b64 {%0,%1}, %2;" : "=f"(r.x), "=f"(r.y) : "l"(v));
  return r;
}
__device__ __forceinline__ float sigmoidf_(float x){ return 1.f/(1.f+__expf(-x)); }

// ---------------- K1: sigmoid + chunk sums ----------------
__global__ void __launch_bounds__(64) k_prep(const float* __restrict__ Q, const float* __restrict__ K){
  int c = blockIdx.x, p = blockIdx.y, d = threadIdx.x;
  const float* Qp = Q + (size_t)(p>>3)*LHD + (size_t)(p&7)*D + d;
  const float* Kp = K + (size_t)(p>>3)*LHD + (size_t)(p&7)*D + d;
  int l0 = c*C;
  int ob = (p*L + l0)*D + d;
  float ks = 0.f, qs = 0.f;
  #pragma unroll 8
  for(int j=0;j<C;j++){
    float qv = sigmoidf_(Qp[(size_t)(l0+j)*HD]);
    float kv = sigmoidf_(Kp[(size_t)(l0+j)*HD]);
    g_sq[ob + j*D] = qv;
    g_sk[ob + j*D] = kv;
    qs += qv; ks += kv;
  }
  g_ksum[(p*NC+c)*D+d] = ks;
  g_qsum[(p*NC+c)*D+d] = qs;
}

// ---------------- K2: gram + sink_incoming / source_outgoing ----------------
// smem: sq (64x68) | sk (64x68) | Ssm (64x65, transposed)
__global__ void __launch_bounds__(64) k_siso(){
  extern __shared__ float sm[];
  float* sqs = sm;
  float* sks = sm + C*SD;
  float* Ssm = sm + 2*C*SD;           // Ssm[j*65+l] = S[l][j]
  __shared__ float rsk[C], rsq[C], sis[C], sos[C], kpre[D], qpre[D];
  int c = blockIdx.x, p = blockIdx.y, l = threadIdx.x;
  int base = (p*L + c*C)*D;
  for(int e=l; e<C*D; e+=C){
    int r = e>>6, col = e&63;
    sqs[r*SD+col] = g_sq[base+e];
    sks[r*SD+col] = g_sk[base+e];
  }
  // fused exclusive prefix of chunk sums (thread = d)
  {
    float a=0.f, b=0.f;
    for(int cp=0; cp<c; cp++){
      a += g_ksum[(p*NC+cp)*D + l];
      b += g_qsum[(p*NC+cp)*D + l];
    }
    kpre[l]=a; qpre[l]=b;
  }
  __syncthreads();

  // row sums + prefix base dots
  float rk=0.f, rq=0.f, b1=0.f, b2=0.f;
  for(int dd=0; dd<D; dd+=4){
    float4 q4 = *(const float4*)(sqs + l*SD + dd);
    float4 k4 = *(const float4*)(sks + l*SD + dd);
    rq += q4.x+q4.y+q4.z+q4.w;
    rk += k4.x+k4.y+k4.z+k4.w;
    b1 += (q4.x+EPSF)*(kpre[dd]+EPSF) + (q4.y+EPSF)*(kpre[dd+1]+EPSF)
        + (q4.z+EPSF)*(kpre[dd+2]+EPSF) + (q4.w+EPSF)*(kpre[dd+3]+EPSF);
    b2 += (k4.x+EPSF)*(qpre[dd]+EPSF) + (k4.y+EPSF)*(qpre[dd+1]+EPSF)
        + (k4.z+EPSF)*(qpre[dd+2]+EPSF) + (k4.w+EPSF)*(qpre[dd+3]+EPSF);
  }
  rsk[l]=rk; rsq[l]=rq;

  // gram: acc[j] = q_l . k_j   (computed ONCE for the whole pipeline)
  float acc[C];
  #pragma unroll
  for(int j=0;j<C;j++) acc[j]=0.f;
  for(int dd=0; dd<D; dd+=4){
    float4 q4 = *(const float4*)(sqs + l*SD + dd);
    #pragma unroll
    for(int j=0;j<C;j++){
      float4 k4 = *(const float4*)(sks + j*SD + dd);  // uniform -> broadcast
      acc[j] = fmaf(q4.x,k4.x, fmaf(q4.y,k4.y, fmaf(q4.z,k4.z, fmaf(q4.w,k4.w, acc[j]))));
    }
  }
  #pragma unroll
  for(int j=0;j<C;j++) Ssm[j*65 + l] = acc[j];
  __syncthreads();

  float dot1=b1, dot2=b2;
  #pragma unroll
  for(int i=0;i<C;i++){
    if(i<=l){
      dot1 += acc[i]        + EPSF*rsk[i];
      dot2 += Ssm[l*65 + i] + EPSF*rsq[i];   // S[i][l]
    }
  }
  float nrm = (float)(c*C + l + 1);
  float si = nrm/dot1, so = nrm/dot2;
  sis[l]=si; sos[l]=so;
  int gl = p*L + c*C + l;
  g_si[gl]=si; g_so[gl]=so; g_rk[gl]=rk; g_rq[gl]=rq;
  __syncthreads();

  // chunk sums of sk*so and sq*si (thread = d; conflict-free column access)
  {
    int d = l; float a1=0.f, a2=0.f;
    for(int j=0;j<C;j++){ a1 += sks[j*SD+d]*sos[j]; a2 += sqs[j*SD+d]*sis[j]; }
    g_kso[(p*NC+c)*D+d] = a1;
    g_qsi[(p*NC+c)*D+d] = a2;
  }
  // store S transposed to global (coalesced)
  int stbase = (p*NC+c)*C*C;
  for(int e=l; e<C*C; e+=C) g_ST[stbase+e] = Ssm[(e>>6)*65 + (e&63)];
}

// ---------------- K3: conserved sink/source (reloads S) ----------------
__global__ void __launch_bounds__(64) k_conserved(){
  extern __shared__ float sm[];
  float* sqs = sm;
  float* sks = sm + C*SD;
  float* STs = sm + 2*C*SD;   // stride SD
  __shared__ float rskv[C], rsqv[C], sis[C], sos[C], kpre[D], qpre[D], facs[C], essh[C];
  int c = blockIdx.x, p = blockIdx.y, l = threadIdx.x;
  int base = (p*L + c*C)*D;
  int stbase = (p*NC+c)*C*C;
  for(int e=l; e<C*D; e+=C){
    int r = e>>6, col = e&63;
    sqs[r*SD+col] = g_sq[base+e];
    sks[r*SD+col] = g_sk[base+e];
    STs[r*SD+col] = g_ST[stbase+e];
  }
  {
    float a=0.f, b=0.f;
    for(int cp=0; cp<c; cp++){
      a += g_kso[(p*NC+cp)*D + l];
      b += g_qsi[(p*NC+cp)*D + l];
    }
    kpre[l]=a; qpre[l]=b;
  }
  int gl = p*L + c*C + l;
  rskv[l]=g_rk[gl]; rsqv[l]=g_rq[gl]; sis[l]=g_si[gl]; sos[l]=g_so[gl];
  __syncthreads();

  float b3=0.f, b4=0.f;
  for(int dd=0; dd<D; dd+=4){
    float4 q4 = *(const float4*)(sqs + l*SD + dd);
    float4 k4 = *(const float4*)(sks + l*SD + dd);
    b3 += (q4.x+EPSF)*(kpre[dd]+EPSF) + (q4.y+EPSF)*(kpre[dd+1]+EPSF)
        + (q4.z+EPSF)*(kpre[dd+2]+EPSF) + (q4.w+EPSF)*(kpre[dd+3]+EPSF);
    b4 += (k4.x+EPSF)*(qpre[dd]+EPSF) + (k4.y+EPSF)*(qpre[dd+1]+EPSF)
        + (k4.z+EPSF)*(qpre[dd+2]+EPSF) + (k4.w+EPSF)*(qpre[dd+3]+EPSF);
  }
  float dot3=b3, dot4=b4;
  #pragma unroll
  for(int i=0;i<C;i++){
    if(i<=l){
      dot3 += sos[i]*(STs[i*SD+l] + EPSF*rskv[i]);   // S[l][i], conflict-free
      dot4 += sis[i]*(STs[l*SD+i] + EPSF*rsqv[i]);   // S[i][l]
    }
  }
  float nrm = (float)(c*C + l + 1);
  float sa  = sigmoidf_(dot3/nrm);
  float cso = dot4/nrm; cso = fminf(1.f, fmaxf(-1.f, cso));
  float es  = __expf(cso);
  g_sa[gl]=sa; g_es[gl]=es;
  essh[l]=es;
  facs[l]=sis[l]/nrm;
  __syncthreads();
  // overwrite g_sq with q_scaled (coalesced)
  for(int e=l; e<C*D; e+=C) g_sq[base+e] = sqs[(e>>6)*SD+(e&63)] * facs[e>>6];
  if(l==0){
    float s=0.f;
    for(int j=0;j<C;j++) s += essh[j];
    g_essum[p*NC+c] = s;
  }
}

// ---------------- K4: v_scaled + chunk KV sums (fused es prefix) ----------------
__global__ void __launch_bounds__(64) k_vkv(const float* __restrict__ V){
  extern __shared__ float sm[];
  float* sks = sm;             // 4096 (unpadded: only col/broadcast access)
  float* vss = sm + C*D;       // 4096
  float* kst = sm + 2*C*D;     // 64*SD staging
  __shared__ float ess[C], comp[C];
  __shared__ float prefsh;
  int c = blockIdx.x, p = blockIdx.y, t = threadIdx.x;
  int base = (p*L + c*C)*D;
  for(int e=t; e<C*D; e+=C) sks[e] = g_sk[base+e];
  ess[t] = g_es[p*L + c*C + t];
  if(t < 32){
    float v = (t < c) ? g_essum[p*NC + t] : 0.f;
    #pragma unroll
    for(int o=16;o;o>>=1) v += __shfl_down_sync(0xffffffffu, v, o);
    if(t==0) prefsh = v;
  }
  __syncthreads();
  if(t==0){
    float run = prefsh;
    for(int j=0;j<C;j++){
      run += ess[j];
      comp[j] = ess[j]/run*(float)(c*C + j + 1);
    }
  }
  __syncthreads();
  const float* Vp = V + (size_t)(p>>3)*LHD + (size_t)(p&7)*D;
  for(int e=t; e<C*D; e+=C){
    int j = e>>6, d2 = e&63;
    float x = Vp[(size_t)(c*C+j)*HD + d2]*comp[j];
    vss[e] = x;
    g_vs[base+e] = x;
  }
  __syncthreads();
  // KV chunk sum (thread t = d row), f32x2 over m
  unsigned long long acc2[32];
  #pragma unroll
  for(int m=0;m<32;m++) acc2[m]=0ull;
  for(int j=0;j<C;j++){
    float a = sks[j*D + t];           // conflict-free column
    unsigned long long a2 = pack2(a, a);
    const double2* vr = (const double2*)(vss + j*D);   // broadcast
    #pragma unroll
    for(int m=0;m<16;m++){
      double2 w = vr[m];
      fma2(acc2[2*m],   a2, (unsigned long long)__double_as_longlong(w.x));
      fma2(acc2[2*m+1], a2, (unsigned long long)__double_as_longlong(w.y));
    }
  }
  #pragma unroll
  for(int m=0;m<32;m++){
    float2 v = unpack2(acc2[m]);
    *(float2*)(kst + t*SD + 2*m) = v;
  }
  __syncthreads();
  size_t kb = (size_t)(p*NC+c)*D*D;
  for(int e=t; e<D*D; e+=C) g_kvc[kb+e] = kst[(e>>6)*SD + (e&63)];
}

// ---------------- K5: exclusive scan of chunk KV sums (register-batched) ----------------
__global__ void k_scan_kv(){
  int p = blockIdx.y;
  int e4 = blockIdx.x*256 + threadIdx.x;     // float4 index within D*D/4=1024
  size_t stride = (size_t)D*D;
  size_t base = (size_t)p*NC*stride + (size_t)e4*4;
  float4 v[NC];
  #pragma unroll
  for(int c=0;c<NC;c++) v[c] = *(const float4*)(g_kvc + base + c*stride);
  float4 run = make_float4(0.f,0.f,0.f,0.f);
  #pragma unroll
  for(int c=0;c<NC;c++){
    float4 t = v[c];
    *(float4*)(g_kvc + base + c*stride) = run;
    run.x += t.x; run.y += t.y; run.z += t.z; run.w += t.w;
  }
}

// ---------------- K6: causal output (reloads S, no gram recompute) ----------------
// smem: qs_scaled (64x68 pad) | ST (4096) | vs (4096) | kvprefix (4096)
__global__ void __launch_bounds__(64) k_out(float* __restrict__ OUT){
  extern __shared__ float sm[];
  float* qss = sm;               // padded
  float* STs = sm + C*SD;        // unpadded (only conflict-free col access)
  float* vss = STs + C*D;
  float* kvs = vss + C*D;
  __shared__ float sa_s[C];
  int c = blockIdx.x, p = blockIdx.y, l = threadIdx.x;
  int base = (p*L + c*C)*D;
  size_t kb = (size_t)(p*NC+c)*D*D;
  int stbase = (p*NC+c)*C*C;
  for(int e=l; e<C*D; e+=C){
    qss[(e>>6)*SD + (e&63)] = g_sq[base+e];   // q_scaled
    STs[e] = g_ST[stbase+e];
    vss[e] = g_vs[base+e];
    kvs[e] = g_kvc[kb+e];
  }
  int gl = p*L + c*C + l;
  sa_s[l] = g_sa[gl];
  float nrm = (float)(c*C + l + 1);
  float fl = g_si[gl]/nrm;       // q_scaled factor for S rescale
  __syncthreads();

  unsigned long long o2[32];
  #pragma unroll
  for(int m=0;m<32;m++) o2[m]=0ull;

  // intra-chunk causal: o += (fl * S[l][i]) * vs[i][:]
  for(int i=0;i<C;i++){
    if(i<=l){
      float s = fl * STs[i*D + l];          // conflict-free column
      unsigned long long s2 = pack2(s, s);
      const double2* vr = (const double2*)(vss + i*D);
      #pragma unroll
      for(int m=0;m<16;m++){
        double2 w = vr[m];
        fma2(o2[2*m],   s2, (unsigned long long)__double_as_longlong(w.x));
        fma2(o2[2*m+1], s2, (unsigned long long)__double_as_longlong(w.y));
      }
    }
  }
  // inter-chunk: o += q_scaled[l] @ KVprefix
  for(int dd=0; dd<D; dd+=4){
    float4 q4 = *(const float4*)(qss + l*SD + dd);
    #pragma unroll
    for(int u=0;u<4;u++){
      float qd = (u==0)?q4.x:(u==1)?q4.y:(u==2)?q4.z:q4.w;
      unsigned long long q2 = pack2(qd, qd);
      const double2* kr = (const double2*)(kvs + (dd+u)*D);
      #pragma unroll
      for(int m=0;m<16;m++){
        double2 w = kr[m];
        fma2(o2[2*m],   q2, (unsigned long long)__double_as_longlong(w.x));
        fma2(o2[2*m+1], q2, (unsigned long long)__double_as_longlong(w.y));
      }
    }
  }
  float sa = sa_s[l];
  __syncthreads();     // qss reads done
  #pragma unroll
  for(int m=0;m<32;m++){
    float2 v = unpack2(o2[m]);
    qss[l*SD + 2*m]   = v.x*sa;
    qss[l*SD + 2*m+1] = v.y*sa;
  }
  __syncthreads();
  float* op = OUT + (size_t)(p>>3)*LHD + (size_t)(c*C)*HD + (size_t)(p&7)*D;
  for(int e=l; e<C*D; e+=C)
    op[(size_t)(e>>6)*HD + (e&63)] = qss[(e>>6)*SD + (e&63)];
}

// ---------------- launch ----------------
extern "C" void kernel_launch(void* const* d_in, const int* in_sizes, int n_in,
                              void* d_out, int out_size){
  const float* Q = (const float*)d_in[0];
  const float* K = (const float*)d_in[1];
  const float* V = (const float*)d_in[2];
  float* OUT = (float*)d_out;

  const int SM_SISO = (2*C*SD + C*65)*sizeof(float);   // 51456
  const int SM_CONS = (3*C*SD)*sizeof(float);          // 52224
  const int SM_VKV  = (2*C*D + C*SD)*sizeof(float);    // 50176
  const int SM_OUT  = (C*SD + 3*C*D)*sizeof(float);    // 66560
  cudaFuncSetAttribute(k_siso,      cudaFuncAttributeMaxDynamicSharedMemorySize, SM_SISO);
  cudaFuncSetAttribute(k_conserved, cudaFuncAttributeMaxDynamicSharedMemorySize, SM_CONS);
  cudaFuncSetAttribute(k_vkv,       cudaFuncAttributeMaxDynamicSharedMemorySize, SM_VKV);
  cudaFuncSetAttribute(k_out,       cudaFuncAttributeMaxDynamicSharedMemorySize, SM_OUT);

  dim3 gpc(NC, P);
  k_prep<<<gpc, 64>>>(Q, K);
  k_siso<<<gpc, 64, SM_SISO>>>();
  k_conserved<<<gpc, 64, SM_CONS>>>();
  k_vkv<<<gpc, 64, SM_VKV>>>(V);
  k_scan_kv<<<dim3(4, P), 256>>>();
  k_out<<<gpc, 64, SM_OUT>>>(OUT);
}